// round 10
// baseline (speedup 1.0000x reference)
#include <cuda_runtime.h>
#include <math.h>

#define NB 8
#define NC 19
#define HW (512 * 512)
#define SMOOTH 1e-08f
#define GRID_X 37
#define NBLOCKS (GRID_X * NB)
#define NTHREADS 256
#define STRIDE (GRID_X * NTHREADS)

__device__ float g_acc[2 * NB * NC];   // [0..152)=tp, [152..304)=den
__device__ unsigned int g_done = 0;

__device__ __forceinline__ float ex2f(float x) {
    asm("ex2.approx.f32 %0, %0;" : "+f"(x));
    return x;
}

// softmax + accumulate for one pixel whose raw logits are in e[0..18]
__device__ __forceinline__ void consume(float* e, int tg,
                                        float* rtp, float* rden) {
    const float LOG2E = 1.4426950408889634f;
#pragma unroll
    for (int c = 0; c < NC; c++) e[c] = ex2f(e[c] * LOG2E);
    // tree-sum to keep the dependence chain shallow
    float s = 0.0f;
    {
        float t0 = e[0] + e[1],   t1 = e[2] + e[3],   t2 = e[4] + e[5];
        float t3 = e[6] + e[7],   t4 = e[8] + e[9],   t5 = e[10] + e[11];
        float t6 = e[12] + e[13], t7 = e[14] + e[15], t8 = e[16] + e[17];
        float u0 = t0 + t1, u1 = t2 + t3, u2 = t4 + t5, u3 = t6 + t7;
        float u4 = t8 + e[18];
        s = ((u0 + u1) + (u2 + u3)) + u4;
    }
    const float r = __fdividef(1.0f, s);
#pragma unroll
    for (int c = 0; c < NC; c++) {
        const float p = e[c] * r;
        rden[c] += p;
        if (tg == c) { rtp[c] += p; rden[c] += 1.0f; }
    }
}

__global__ __launch_bounds__(NTHREADS, 2) void tversky_fused_kernel(
    const float* __restrict__ pred, const int* __restrict__ target,
    float* __restrict__ out) {
    const int b = blockIdx.y;
    const float* __restrict__ ps = pred + (size_t)b * NC * HW;
    const int* __restrict__ tgp = target + (size_t)b * HW;
    const int tid = threadIdx.x;

    __shared__ float s_acc[2 * NC];   // tp, den
    __shared__ int s_is_last;
    if (tid < 2 * NC) s_acc[tid] = 0.0f;
    __syncthreads();

    float rtp[NC], rden[NC];
#pragma unroll
    for (int c = 0; c < NC; c++) { rtp[c] = 0.0f; rden[c] = 0.0f; }

    float eA[NC], eB[NC];
    int tgA = 0, tgB = 0;

    int idx = blockIdx.x * NTHREADS + tid;
    if (idx < HW) {
#pragma unroll
        for (int c = 0; c < NC; c++) eA[c] = ps[(size_t)c * HW + idx];
        tgA = tgp[idx];
    }
    // software-pipelined: prefetch next burst into the other buffer,
    // then consume the current one — loads stay in flight under compute
    while (idx < HW) {
        const int i2 = idx + STRIDE;
        if (i2 < HW) {
#pragma unroll
            for (int c = 0; c < NC; c++) eB[c] = ps[(size_t)c * HW + i2];
            tgB = tgp[i2];
        }
        consume(eA, tgA, rtp, rden);
        idx = i2;
        if (idx >= HW) break;

        const int i3 = idx + STRIDE;
        if (i3 < HW) {
#pragma unroll
            for (int c = 0; c < NC; c++) eA[c] = ps[(size_t)c * HW + i3];
            tgA = tgp[i3];
        }
        consume(eB, tgB, rtp, rden);
        idx = i3;
    }

    // warp-level reduction of the 38 accumulators
#pragma unroll
    for (int c = 0; c < NC; c++) {
#pragma unroll
        for (int off = 16; off > 0; off >>= 1) {
            rtp[c]  += __shfl_down_sync(0xFFFFFFFFu, rtp[c],  off);
            rden[c] += __shfl_down_sync(0xFFFFFFFFu, rden[c], off);
        }
    }
    if ((tid & 31) == 0) {
#pragma unroll
        for (int c = 0; c < NC; c++) {
            atomicAdd(&s_acc[c], rtp[c]);
            atomicAdd(&s_acc[NC + c], rden[c]);
        }
    }
    __syncthreads();

    // block -> global (38 atomics from first 38 threads)
    if (tid < 2 * NC) {
        const int sec = tid / NC;
        const int c = tid - sec * NC;
        atomicAdd(&g_acc[sec * NB * NC + b * NC + c], s_acc[tid]);
    }

    // last-block-done epilogue
    __threadfence();
    if (tid == 0) {
        unsigned int n = atomicAdd(&g_done, 1u);
        s_is_last = (n == NBLOCKS - 1);
    }
    __syncthreads();
    if (!s_is_last) return;

    __shared__ float s_red[NTHREADS];
    float v = 0.0f;
    if (tid < NB * NC) {
        const float tp = __ldcg(&g_acc[tid]);
        const float dn = __ldcg(&g_acc[NB * NC + tid]);
        v = 1.0f - (tp + SMOOTH) / (0.5f * dn + SMOOTH);  // alpha=beta=0.5
    }
    s_red[tid] = v;
    __syncthreads();
#pragma unroll
    for (int off = NTHREADS / 2; off > 0; off >>= 1) {
        if (tid < off) s_red[tid] += s_red[tid + off];
        __syncthreads();
    }
    if (tid == 0) {
        out[0] = s_red[0] / (float)(NB * NC);
        g_done = 0u;
    }
    for (int i = tid; i < 2 * NB * NC; i += NTHREADS) g_acc[i] = 0.0f;
}

extern "C" void kernel_launch(void* const* d_in, const int* in_sizes, int n_in,
                              void* d_out, int out_size) {
    const float* pred = (const float*)d_in[0];
    const int* target = (const int*)d_in[1];
    float* out = (float*)d_out;

    dim3 grid(GRID_X, NB);
    tversky_fused_kernel<<<grid, NTHREADS>>>(pred, target, out);
}